// round 1
// baseline (speedup 1.0000x reference)
#include <cuda_runtime.h>
#include <math.h>

#define HDC_D      10000
#define HDC_T      2048
#define HDC_LEVELS 100
#define TPB        64        // 2 warps per block; one thread per D-column
#define EFFW       30        // effective (owned) columns per warp (lanes 2..31)
#define EFFB       60        // per block
#define NBD        167       // ceil(10000 / 60)
#define NT         4         // time-chunk split of the 2046 product terms
#define MTOT       2046      // T - 2 product terms
#define MCHUNK     512       // ceil(2046 / 4)

// idx[t] packed as ushort4, each pre-multiplied by the shared-tile row stride (TPB)
__device__ ushort4 g_idx[HDC_T];
// partial sums per time-chunk; written with plain stores (disjoint) -> deterministic
__device__ float   g_partial[NT * HDC_D];

__global__ void prep_idx_kernel(const float* __restrict__ inp) {
    int t = blockIdx.x * blockDim.x + threadIdx.x;
    if (t >= HDC_T) return;
    float4 v = reinterpret_cast<const float4*>(inp)[t];
    // jnp.round = round half to even -> __float2int_rn
    int i0 = min(max(__float2int_rn(v.x * 99.0f), 0), 99);
    int i1 = min(max(__float2int_rn(v.y * 99.0f), 0), 99);
    int i2 = min(max(__float2int_rn(v.z * 99.0f), 0), 99);
    int i3 = min(max(__float2int_rn(v.w * 99.0f), 0), 99);
    g_idx[t] = make_ushort4((unsigned short)(i0 * TPB), (unsigned short)(i1 * TPB),
                            (unsigned short)(i2 * TPB), (unsigned short)(i3 * TPB));
}

__global__ void __launch_bounds__(TPB)
hv_kernel(const float* __restrict__ keys, const float* __restrict__ level) {
    __shared__ float lvl[HDC_LEVELS * TPB];   // 100 x 64 floats = 25.6 KB

    const int tid  = threadIdx.x;
    const int warp = tid >> 5;
    const int lane = tid & 31;
    const int ct   = blockIdx.y;

    // this lane's global column (lanes 0,1 are the left halo)
    int gcol = blockIdx.x * EFFB + warp * EFFW - 2 + lane;   // in [-2, 10019]
    int g = gcol;
    if (g < 0)       g += HDC_D;
    if (g >= HDC_D)  g -= HDC_D;

    // stage the level_hv column tile into shared (coalesced per row)
    #pragma unroll 5
    for (int r = 0; r < HDC_LEVELS; r++) {
        lvl[r * TPB + tid] = level[r * HDC_D + g];
    }
    const float k0 = keys[0 * HDC_D + g];
    const float k1 = keys[1 * HDC_D + g];
    const float k2 = keys[2 * HDC_D + g];
    const float k3 = keys[3 * HDC_D + g];
    __syncthreads();

    const int m0 = ct * MCHUNK;
    const int m1 = min(m0 + MCHUNK, MTOT);
    const int t0 = m0;
    const int t1 = m1 + 2;          // need hv rows m0 .. m1+1

    float h1 = 0.0f, h2 = 0.0f, acc = 0.0f;

    #pragma unroll 4
    for (int t = t0; t < t1; t++) {
        ushort4 u = g_idx[t];       // broadcast LDG.64, L1-resident
        float l0 = lvl[u.x + tid];
        float l1 = lvl[u.y + tid];
        float l2 = lvl[u.z + tid];
        float l3 = lvl[u.w + tid];
        float hv = fmaf(k0, l0, fmaf(k1, l1, fmaf(k2, l2, k3 * l3)));
        // hv[t-2, d-2] from lane-2, hv[t-1, d-1] from lane-1
        float a = __shfl_up_sync(0xffffffffu, h2, 2);
        float b = __shfl_up_sync(0xffffffffu, h1, 1);
        // zero-initialized history makes the first two iterations contribute 0
        acc = fmaf(a * b, hv, acc);
        h2 = h1;
        h1 = hv;
    }

    // lanes >= 2 own column gcol (guaranteed >= 0); skip past-the-end columns
    if (lane >= 2 && gcol < HDC_D) {
        g_partial[ct * HDC_D + gcol] = acc;
    }
}

__global__ void epilogue_kernel(const float* __restrict__ feat,
                                const float* __restrict__ W3,
                                const float* __restrict__ b3,
                                const float* __restrict__ W6,
                                const float* __restrict__ b6,
                                float* __restrict__ out) {
    int d = blockIdx.x * blockDim.x + threadIdx.x;
    if (d >= HDC_D) return;

    float s = (g_partial[d] + g_partial[HDC_D + d]) +
              (g_partial[2 * HDC_D + d] + g_partial[3 * HDC_D + d]);

    const int S[8] = {0, 9, 12, 15, 18, 21, 24, 27};
    float h[8];
    #pragma unroll
    for (int k = 0; k < 8; k++) {
        const float* w = W3 + (k * HDC_D + d) * 3;
        float p = w[0] * feat[S[k]] + w[1] * feat[S[k] + 1] + w[2] * feat[S[k] + 2];
        h[k] = cosf(p + b3[k * HDC_D + d]) * sinf(p);
    }

    float p6 = 0.0f;
    #pragma unroll
    for (int i = 0; i < 6; i++) p6 += W6[d * 6 + i] * feat[3 + i];
    float h6 = cosf(p6 + b6[d]) * sinf(p6);

    // match reference multiply order exactly
    float o = s * h[0];
    o *= (h6 + h[7]);
    o *= (h[1] + h[2] + h[3]);
    o *= (h[4] + h[5] + h[6]);
    out[d] = (o > 0.0f) ? 1.0f : -1.0f;
}

extern "C" void kernel_launch(void* const* d_in, const int* in_sizes, int n_in,
                              void* d_out, int out_size) {
    const float* inp   = (const float*)d_in[0];
    const float* feat  = (const float*)d_in[1];
    const float* keys  = (const float*)d_in[2];
    const float* level = (const float*)d_in[3];
    const float* W3    = (const float*)d_in[4];
    const float* b3    = (const float*)d_in[5];
    const float* W6    = (const float*)d_in[6];
    const float* b6    = (const float*)d_in[7];
    float* out = (float*)d_out;

    prep_idx_kernel<<<2, 1024>>>(inp);
    dim3 grid(NBD, NT);
    hv_kernel<<<grid, TPB>>>(keys, level);
    epilogue_kernel<<<(HDC_D + 127) / 128, 128>>>(feat, W3, b3, W6, b6, out);
}

// round 2
// speedup vs baseline: 1.0012x; 1.0012x over previous
#include <cuda_runtime.h>
#include <math.h>

#define HDC_D      10000
#define HDC_T      2048
#define HDC_LEVELS 100
#define TPB        64        // 2 warps; each thread owns 2 adjacent columns (f32x2)
#define EFFW       62        // owned columns per warp (lane 0 pair is halo)
#define EFFB       124       // owned columns per block
#define NBD        81        // ceil(10000 / 124)
#define NT         8         // time-chunk split
#define MTOT       2046      // T - 2 product terms
#define MCHUNK     256       // terms per chunk

// partial sums per time-chunk; disjoint plain stores -> deterministic
__device__ float g_partial[NT * HDC_D];

// ---------- packed f32x2 helpers (Blackwell) ----------
__device__ __forceinline__ unsigned long long pk2(float lo, float hi) {
    unsigned long long r;
    asm("mov.b64 %0, {%1, %2};" : "=l"(r) : "f"(lo), "f"(hi));
    return r;
}
__device__ __forceinline__ void up2(unsigned long long v, float& lo, float& hi) {
    asm("mov.b64 {%0, %1}, %2;" : "=f"(lo), "=f"(hi) : "l"(v));
}
__device__ __forceinline__ unsigned long long fma2(unsigned long long a,
                                                   unsigned long long b,
                                                   unsigned long long c) {
    unsigned long long d;
    asm("fma.rn.f32x2 %0, %1, %2, %3;" : "=l"(d) : "l"(a), "l"(b), "l"(c));
    return d;
}
__device__ __forceinline__ unsigned long long mul2(unsigned long long a,
                                                   unsigned long long b) {
    unsigned long long d;
    asm("mul.rn.f32x2 %0, %1, %2;" : "=l"(d) : "l"(a), "l"(b));
    return d;
}

// dynamic smem layout:
//   float tile[2][HDC_LEVELS][64]          (51200 B)
//   uint4 sidx[MCHUNK + 2]                 (4128 B)  -- row offsets pre-scaled by 64
#define TILE_FLOATS (2 * HDC_LEVELS * 64)
#define SMEM_BYTES  (TILE_FLOATS * 4 + (MCHUNK + 2) * 16)

__global__ void __launch_bounds__(TPB)
hv_kernel(const float* __restrict__ inp,
          const float* __restrict__ keys,
          const float* __restrict__ level) {
    extern __shared__ float smem[];
    float* tile = smem;
    uint4* sidx = reinterpret_cast<uint4*>(smem + TILE_FLOATS);

    const int tid  = threadIdx.x;
    const int warp = tid >> 5;
    const int lane = tid & 31;
    const int ct   = blockIdx.y;

    const int m0    = ct * MCHUNK;
    const int iters = min(MCHUNK, MTOT - m0) + 2;   // hv rows m0 .. m0+iters-1
    const int t0    = m0;

    // --- fused index prep: this chunk's idx -> shared (pre-scaled by 64) ---
    for (int j = tid; j < iters; j += TPB) {
        float4 v = reinterpret_cast<const float4*>(inp)[t0 + j];
        // jnp.round = round half to even -> __float2int_rn
        unsigned i0 = (unsigned)min(max(__float2int_rn(v.x * 99.0f), 0), 99);
        unsigned i1 = (unsigned)min(max(__float2int_rn(v.y * 99.0f), 0), 99);
        unsigned i2 = (unsigned)min(max(__float2int_rn(v.z * 99.0f), 0), 99);
        unsigned i3 = (unsigned)min(max(__float2int_rn(v.w * 99.0f), 0), 99);
        sidx[j] = make_uint4(i0 * 64u, i1 * 64u, i2 * 64u, i3 * 64u);
    }

    // --- column assignment: thread pair (p0, p0+1); lane 0 pair is left halo ---
    const int p0 = blockIdx.x * EFFB + warp * EFFW - 2 + 2 * lane;  // even
    int g0 = p0;
    if (g0 < 0)        g0 += HDC_D;   // circular roll in d
    if (g0 >= HDC_D)   g0 -= HDC_D;
    // g0 is even and < HDC_D, so g0+1 is valid (no wrap mid-pair)

    // --- stage level tile (100 rows x 2 cols per thread, float2) ---
    float* mycol = tile + warp * HDC_LEVELS * 64 + 2 * lane;
    #pragma unroll 4
    for (int r = 0; r < HDC_LEVELS; r++) {
        float2 v = *reinterpret_cast<const float2*>(level + r * HDC_D + g0);
        *reinterpret_cast<float2*>(mycol + r * 64) = v;
    }
    const unsigned long long K0 = pk2(keys[g0],             keys[g0 + 1]);
    const unsigned long long K1 = pk2(keys[HDC_D + g0],     keys[HDC_D + g0 + 1]);
    const unsigned long long K2 = pk2(keys[2*HDC_D + g0],   keys[2*HDC_D + g0 + 1]);
    const unsigned long long K3 = pk2(keys[3*HDC_D + g0],   keys[3*HDC_D + g0 + 1]);
    __syncthreads();

    const float* wt = tile + warp * HDC_LEVELS * 64 + 2 * lane;

    float h1lo = 0.0f, h1hi = 0.0f, h2lo = 0.0f, h2hi = 0.0f;
    unsigned long long acc = 0ULL;   // packed (0.0f, 0.0f)

    #pragma unroll 4
    for (int j = 0; j < iters; j++) {
        uint4 u = sidx[j];   // broadcast LDS.128
        unsigned long long L0 = *reinterpret_cast<const unsigned long long*>(wt + u.x);
        unsigned long long L1 = *reinterpret_cast<const unsigned long long*>(wt + u.y);
        unsigned long long L2 = *reinterpret_cast<const unsigned long long*>(wt + u.z);
        unsigned long long L3 = *reinterpret_cast<const unsigned long long*>(wt + u.w);
        unsigned long long H  = fma2(K0, L0, fma2(K1, L1, fma2(K2, L2, mul2(K3, L3))));

        // A = hv[t-2] at (d-2, d-1) = lane-1's full h2 pair
        float a_lo = __shfl_up_sync(0xffffffffu, h2lo, 1);
        float a_hi = __shfl_up_sync(0xffffffffu, h2hi, 1);
        // B = hv[t-1] at (d-1, d) = (lane-1's h1.hi, own h1.lo)
        float b_lo = __shfl_up_sync(0xffffffffu, h1hi, 1);
        unsigned long long A = pk2(a_lo, a_hi);
        unsigned long long B = pk2(b_lo, h1lo);

        acc = fma2(mul2(A, B), H, acc);   // zero history -> first 2 iters add 0

        h2lo = h1lo; h2hi = h1hi;
        up2(H, h1lo, h1hi);
    }

    // lanes >= 1 own their pair; skip past-the-end columns (last block only)
    if (lane >= 1 && p0 < HDC_D) {
        float alo, ahi;
        up2(acc, alo, ahi);
        *reinterpret_cast<float2*>(&g_partial[ct * HDC_D + p0]) = make_float2(alo, ahi);
    }
}

__global__ void epilogue_kernel(const float* __restrict__ feat,
                                const float* __restrict__ W3,
                                const float* __restrict__ b3,
                                const float* __restrict__ W6,
                                const float* __restrict__ b6,
                                float* __restrict__ out) {
    int d = blockIdx.x * blockDim.x + threadIdx.x;
    if (d >= HDC_D) return;

    float s = 0.0f;
    #pragma unroll
    for (int c = 0; c < NT; c++) s += g_partial[c * HDC_D + d];

    const int S[8] = {0, 9, 12, 15, 18, 21, 24, 27};
    float h[8];
    #pragma unroll
    for (int k = 0; k < 8; k++) {
        const float* w = W3 + (k * HDC_D + d) * 3;
        float p = w[0] * feat[S[k]] + w[1] * feat[S[k] + 1] + w[2] * feat[S[k] + 2];
        h[k] = cosf(p + b3[k * HDC_D + d]) * sinf(p);
    }

    float p6 = 0.0f;
    #pragma unroll
    for (int i = 0; i < 6; i++) p6 += W6[d * 6 + i] * feat[3 + i];
    float h6 = cosf(p6 + b6[d]) * sinf(p6);

    // match reference multiply order exactly
    float o = s * h[0];
    o *= (h6 + h[7]);
    o *= (h[1] + h[2] + h[3]);
    o *= (h[4] + h[5] + h[6]);
    out[d] = (o > 0.0f) ? 1.0f : -1.0f;
}

extern "C" void kernel_launch(void* const* d_in, const int* in_sizes, int n_in,
                              void* d_out, int out_size) {
    const float* inp   = (const float*)d_in[0];
    const float* feat  = (const float*)d_in[1];
    const float* keys  = (const float*)d_in[2];
    const float* level = (const float*)d_in[3];
    const float* W3    = (const float*)d_in[4];
    const float* b3    = (const float*)d_in[5];
    const float* W6    = (const float*)d_in[6];
    const float* b6    = (const float*)d_in[7];
    float* out = (float*)d_out;

    cudaFuncSetAttribute(hv_kernel, cudaFuncAttributeMaxDynamicSharedMemorySize,
                         SMEM_BYTES);

    dim3 grid(NBD, NT);
    hv_kernel<<<grid, TPB, SMEM_BYTES>>>(inp, keys, level);
    epilogue_kernel<<<(HDC_D + 127) / 128, 128>>>(feat, W3, b3, W6, b6, out);
}

// round 4
// speedup vs baseline: 1.6667x; 1.6646x over previous
#include <cuda_runtime.h>
#include <math.h>

#define HDC_D      10000
#define HDC_T      2048
#define HDC_LEVELS 100
#define TPB        128       // 4 warps share one tile; each warp = distinct time-chunk
#define EFFB       62        // owned columns per block (lane 0 pair is halo)
#define NBD        162       // ceil(10000 / 62)
#define NT         16        // time-chunks (4 per block in y, 4 warps)
#define MTOT       2046      // T - 2 product terms
#define MCHUNK     128       // terms per chunk

// idx[t] packed as ushort4, pre-scaled by tile row stride (64 floats)
__device__ ushort4 g_idx[HDC_T];
// partial sums per time-chunk; disjoint plain stores -> deterministic
__device__ float   g_partial[NT * HDC_D];

// ---------- packed f32x2 helpers (Blackwell) ----------
__device__ __forceinline__ unsigned long long pk2(float lo, float hi) {
    unsigned long long r;
    asm("mov.b64 %0, {%1, %2};" : "=l"(r) : "f"(lo), "f"(hi));
    return r;
}
__device__ __forceinline__ void up2(unsigned long long v, float& lo, float& hi) {
    asm("mov.b64 {%0, %1}, %2;" : "=f"(lo), "=f"(hi) : "l"(v));
}
__device__ __forceinline__ unsigned long long fma2(unsigned long long a,
                                                   unsigned long long b,
                                                   unsigned long long c) {
    unsigned long long d;
    asm("fma.rn.f32x2 %0, %1, %2, %3;" : "=l"(d) : "l"(a), "l"(b), "l"(c));
    return d;
}
__device__ __forceinline__ unsigned long long mul2(unsigned long long a,
                                                   unsigned long long b) {
    unsigned long long d;
    asm("mul.rn.f32x2 %0, %1, %2;" : "=l"(d) : "l"(a), "l"(b));
    return d;
}

__global__ void prep_idx_kernel(const float* __restrict__ inp) {
    int t = blockIdx.x * blockDim.x + threadIdx.x;
    if (t >= HDC_T) return;
    float4 v = reinterpret_cast<const float4*>(inp)[t];
    // jnp.round = round half to even -> __float2int_rn
    int i0 = min(max(__float2int_rn(v.x * 99.0f), 0), 99);
    int i1 = min(max(__float2int_rn(v.y * 99.0f), 0), 99);
    int i2 = min(max(__float2int_rn(v.z * 99.0f), 0), 99);
    int i3 = min(max(__float2int_rn(v.w * 99.0f), 0), 99);
    g_idx[t] = make_ushort4((unsigned short)(i0 * 64), (unsigned short)(i1 * 64),
                            (unsigned short)(i2 * 64), (unsigned short)(i3 * 64));
}

__global__ void __launch_bounds__(TPB)
hv_kernel(const float* __restrict__ keys, const float* __restrict__ level) {
    __shared__ float tile[HDC_LEVELS * 64];   // 25.6 KB, shared by all 4 warps

    const int tid  = threadIdx.x;
    const int warp = tid >> 5;
    const int lane = tid & 31;
    const int ct   = blockIdx.y * 4 + warp;   // this warp's time-chunk

    const int gstart = blockIdx.x * EFFB - 2; // global column of tile col 0 (even)

    // --- stage the 100x64 level tile cooperatively (float2, coalesced) ---
    for (int i = tid; i < HDC_LEVELS * 32; i += TPB) {
        int row = i >> 5;
        int c2  = (i & 31) * 2;
        int g = gstart + c2;
        if (g < 0)       g += HDC_D;
        if (g >= HDC_D)  g -= HDC_D;
        *reinterpret_cast<float2*>(&tile[row * 64 + c2]) =
            *reinterpret_cast<const float2*>(&level[row * HDC_D + g]);
    }

    // --- per-thread column pair ---
    const int p0 = gstart + 2 * lane;         // even; lane 0 pair is left halo
    int g0 = p0;
    if (g0 < 0)       g0 += HDC_D;
    if (g0 >= HDC_D)  g0 -= HDC_D;

    const float2 kk0 = *reinterpret_cast<const float2*>(&keys[g0]);
    const float2 kk1 = *reinterpret_cast<const float2*>(&keys[HDC_D + g0]);
    const float2 kk2 = *reinterpret_cast<const float2*>(&keys[2 * HDC_D + g0]);
    const float2 kk3 = *reinterpret_cast<const float2*>(&keys[3 * HDC_D + g0]);
    const unsigned long long K0 = pk2(kk0.x, kk0.y);
    const unsigned long long K1 = pk2(kk1.x, kk1.y);
    const unsigned long long K2 = pk2(kk2.x, kk2.y);
    const unsigned long long K3 = pk2(kk3.x, kk3.y);
    __syncthreads();

    const int m0    = ct * MCHUNK;
    const int iters = min(MCHUNK, MTOT - m0) + 2;
    const float* wt = tile + 2 * lane;

    float h1lo = 0.0f, h1hi = 0.0f, h2lo = 0.0f, h2hi = 0.0f;
    unsigned long long acc = 0ULL;   // packed (0.0f, 0.0f)

    #pragma unroll 4
    for (int j = 0; j < iters; j++) {
        ushort4 u = g_idx[m0 + j];   // broadcast LDG.64, L1-resident
        unsigned long long L0 = *reinterpret_cast<const unsigned long long*>(wt + u.x);
        unsigned long long L1 = *reinterpret_cast<const unsigned long long*>(wt + u.y);
        unsigned long long L2 = *reinterpret_cast<const unsigned long long*>(wt + u.z);
        unsigned long long L3 = *reinterpret_cast<const unsigned long long*>(wt + u.w);
        unsigned long long H  = fma2(K0, L0, fma2(K1, L1, fma2(K2, L2, mul2(K3, L3))));

        // A = hv[t-2] at (d-2, d-1) = lane-1's full h2 pair
        float a_lo = __shfl_up_sync(0xffffffffu, h2lo, 1);
        float a_hi = __shfl_up_sync(0xffffffffu, h2hi, 1);
        // B = hv[t-1] at (d-1, d) = (lane-1's h1.hi, own h1.lo)
        float b_lo = __shfl_up_sync(0xffffffffu, h1hi, 1);
        unsigned long long A = pk2(a_lo, a_hi);
        unsigned long long B = pk2(b_lo, h1lo);

        acc = fma2(mul2(A, B), H, acc);   // zero history -> first 2 iters add 0

        h2lo = h1lo; h2hi = h1hi;
        up2(H, h1lo, h1hi);
    }

    // lanes >= 1 own their pair; skip past-the-end columns (last block only)
    if (lane >= 1 && p0 < HDC_D) {
        float alo, ahi;
        up2(acc, alo, ahi);
        *reinterpret_cast<float2*>(&g_partial[ct * HDC_D + p0]) = make_float2(alo, ahi);
    }
}

__global__ void epilogue_kernel(const float* __restrict__ feat,
                                const float* __restrict__ W3,
                                const float* __restrict__ b3,
                                const float* __restrict__ W6,
                                const float* __restrict__ b6,
                                float* __restrict__ out) {
    int d = blockIdx.x * blockDim.x + threadIdx.x;
    if (d >= HDC_D) return;

    // ---- issue ALL independent loads first (maximize MLP) ----
    float pr[NT];
    #pragma unroll
    for (int c = 0; c < NT; c++) pr[c] = g_partial[c * HDC_D + d];

    float w3v[8][3], b3v[8];
    #pragma unroll
    for (int k = 0; k < 8; k++) {
        const float* w = W3 + (k * HDC_D + d) * 3;
        w3v[k][0] = w[0]; w3v[k][1] = w[1]; w3v[k][2] = w[2];
        b3v[k] = b3[k * HDC_D + d];
    }
    float w6v[6];
    #pragma unroll
    for (int i = 0; i < 6; i++) w6v[i] = W6[d * 6 + i];
    float b6v = b6[d];

    float fv[30];
    #pragma unroll
    for (int i = 0; i < 30; i++) fv[i] = feat[i];   // L1-resident broadcast

    // ---- compute ----
    float s = 0.0f;
    #pragma unroll
    for (int c = 0; c < NT; c++) s += pr[c];

    const int S[8] = {0, 9, 12, 15, 18, 21, 24, 27};
    float h[8];
    #pragma unroll
    for (int k = 0; k < 8; k++) {
        float p = w3v[k][0] * fv[S[k]] + w3v[k][1] * fv[S[k] + 1] + w3v[k][2] * fv[S[k] + 2];
        h[k] = cosf(p + b3v[k]) * sinf(p);
    }

    float p6 = 0.0f;
    #pragma unroll
    for (int i = 0; i < 6; i++) p6 += w6v[i] * fv[3 + i];
    float h6 = cosf(p6 + b6v) * sinf(p6);

    // match reference multiply order exactly
    float o = s * h[0];
    o *= (h6 + h[7]);
    o *= (h[1] + h[2] + h[3]);
    o *= (h[4] + h[5] + h[6]);
    out[d] = (o > 0.0f) ? 1.0f : -1.0f;
}

extern "C" void kernel_launch(void* const* d_in, const int* in_sizes, int n_in,
                              void* d_out, int out_size) {
    const float* inp   = (const float*)d_in[0];
    const float* feat  = (const float*)d_in[1];
    const float* keys  = (const float*)d_in[2];
    const float* level = (const float*)d_in[3];
    const float* W3    = (const float*)d_in[4];
    const float* b3    = (const float*)d_in[5];
    const float* W6    = (const float*)d_in[6];
    const float* b6    = (const float*)d_in[7];
    float* out = (float*)d_out;

    prep_idx_kernel<<<4, 512>>>(inp);
    dim3 grid(NBD, NT / 4);
    hv_kernel<<<grid, TPB>>>(keys, level);
    epilogue_kernel<<<(HDC_D + 255) / 256, 256>>>(feat, W3, b3, W6, b6, out);
}